// round 2
// baseline (speedup 1.0000x reference)
#include <cuda_runtime.h>
#include <math.h>

// Problem constants (fixed shapes from reference)
#define D_DIM   1024
#define F_DIM   704
#define E_NUM   64
#define NTOK    1024      // B*T = 2*512
#define TOPK    6
#define FS_DIM  1408
#define NPAIR   (NTOK*TOPK)   // 6144

// ---- scratch (static device arrays; no allocation allowed) ----
__device__ float g_hbuf[NPAIR * F_DIM];      // up-proj activations per pair
__device__ float g_dbuf[NPAIR * D_DIM];      // weighted down-proj per pair
__device__ float g_sh[NTOK * FS_DIM];        // shared-expert hidden
__device__ int   g_count[E_NUM];
__device__ int   g_offset[E_NUM];
__device__ int   g_cursor[E_NUM];
__device__ int   g_tok_expert[NTOK*TOPK];
__device__ float g_tok_w[NTOK*TOPK];
__device__ int   g_tok_pair[NTOK*TOPK];
__device__ int   g_pair_token[NPAIR];
__device__ float g_pair_w[NPAIR];
__device__ float g_scores_scratch[NTOK * E_NUM];

// ---------------------------------------------------------------------------
__global__ void init_kernel() {
    int i = threadIdx.x;
    if (i < E_NUM) { g_count[i] = 0; g_cursor[i] = 0; }
}

// ---------------------------------------------------------------------------
// Gate: logits = x @ w_gate^T ; scores = sigmoid + bias ; top-6 ; normalize.
// One block per token, 128 threads.
__global__ void gate_kernel(const float* __restrict__ x,
                            const float* __restrict__ wg,
                            const float* __restrict__ gb,
                            float* __restrict__ scores_out) {
    __shared__ float xs[D_DIM];
    __shared__ float sc[E_NUM];
    int t = blockIdx.x;
    int tid = threadIdx.x;

    const float4* xv = (const float4*)(x + (size_t)t * D_DIM);
    float4* xsv = (float4*)xs;
    for (int i = tid; i < D_DIM/4; i += 128) xsv[i] = xv[i];
    __syncthreads();

    if (tid < E_NUM) {
        const float4* wv = (const float4*)(wg + (size_t)tid * D_DIM);
        float acc = 0.f;
        #pragma unroll 8
        for (int i = 0; i < D_DIM/4; i++) {
            float4 a = xsv[i]; float4 b = wv[i];
            acc += a.x*b.x + a.y*b.y + a.z*b.z + a.w*b.w;
        }
        float s = 1.f/(1.f + expf(-acc)) + gb[tid];
        sc[tid] = s;
        scores_out[(size_t)t * E_NUM + tid] = s;
    }
    __syncthreads();

    if (tid == 0) {
        float tmp[E_NUM];
        for (int i = 0; i < E_NUM; i++) tmp[i] = sc[i];
        int   sel[TOPK]; float selw[TOPK];
        float wsum = 0.f;
        for (int k = 0; k < TOPK; k++) {
            int bi = 0; float bv = tmp[0];
            for (int i = 1; i < E_NUM; i++)
                if (tmp[i] > bv) { bv = tmp[i]; bi = i; }
            sel[k] = bi; selw[k] = bv; wsum += bv;
            tmp[bi] = -1e30f;
        }
        float inv = 1.f / wsum;
        for (int k = 0; k < TOPK; k++) {
            int e = sel[k];
            g_tok_expert[t*TOPK + k] = e;
            g_tok_w[t*TOPK + k] = selw[k] * inv;
            atomicAdd(&g_count[e], 1);
        }
    }
}

// ---------------------------------------------------------------------------
__global__ void scan_kernel() {
    if (threadIdx.x == 0) {
        int acc = 0;
        for (int e = 0; e < E_NUM; e++) { g_offset[e] = acc; acc += g_count[e]; }
    }
}

__global__ void assign_kernel() {
    int t = blockIdx.x * blockDim.x + threadIdx.x;
    if (t >= NTOK) return;
    for (int k = 0; k < TOPK; k++) {
        int e = g_tok_expert[t*TOPK + k];
        int slot = atomicAdd(&g_cursor[e], 1);
        int p = g_offset[e] + slot;
        g_pair_token[p] = t;
        g_pair_w[p] = g_tok_w[t*TOPK + k];
        g_tok_pair[t*TOPK + k] = p;
    }
}

// ---------------------------------------------------------------------------
// Routed up-proj: for expert e, h = silu(x@W1_e) * (x@W3_e)
// BM=32, BN=64, BK=32; 256 threads; 2x4 register tile per thread, 2 matrices.
// grid: (F/64=11, E, 32 mtiles)
__global__ void __launch_bounds__(256)
up_routed_kernel(const float* __restrict__ x,
                 const float* __restrict__ w1,
                 const float* __restrict__ w3) {
    int e = blockIdx.y;
    int cnt = g_count[e];
    int row0 = blockIdx.z * 32;
    if (row0 >= cnt) return;
    int base = g_offset[e];
    int f0 = blockIdx.x * 64;

    __shared__ float xs[32][36];
    __shared__ float w1s[32][64];
    __shared__ float w3s[32][64];
    __shared__ int toks[32];

    int tid = threadIdx.x;
    if (tid < 32) {
        int r = row0 + tid;
        toks[tid] = (r < cnt) ? g_pair_token[base + r] : -1;
    }
    __syncthreads();

    int tx = tid & 15, ty = tid >> 4;
    float acc1[2][4] = {}, acc3[2][4] = {};
    const float* w1e = w1 + (size_t)e * D_DIM * F_DIM;
    const float* w3e = w3 + (size_t)e * D_DIM * F_DIM;

    for (int k0 = 0; k0 < D_DIM; k0 += 32) {
        {
            int r = tid >> 3, v = tid & 7;
            int tok = toks[r];
            float4 val = make_float4(0.f, 0.f, 0.f, 0.f);
            if (tok >= 0) val = *(const float4*)(x + (size_t)tok * D_DIM + k0 + v*4);
            *(float4*)&xs[r][v*4] = val;
        }
        #pragma unroll
        for (int i = 0; i < 2; i++) {
            int idx = tid + i*256;
            int kr = idx >> 4, c4 = idx & 15;
            *(float4*)&w1s[kr][c4*4] = *(const float4*)(w1e + (size_t)(k0+kr)*F_DIM + f0 + c4*4);
            *(float4*)&w3s[kr][c4*4] = *(const float4*)(w3e + (size_t)(k0+kr)*F_DIM + f0 + c4*4);
        }
        __syncthreads();
        #pragma unroll
        for (int kk = 0; kk < 32; kk++) {
            float a0 = xs[ty*2][kk], a1 = xs[ty*2+1][kk];
            float4 b1 = *(float4*)&w1s[kk][tx*4];
            float4 b3 = *(float4*)&w3s[kk][tx*4];
            acc1[0][0] += a0*b1.x; acc1[0][1] += a0*b1.y; acc1[0][2] += a0*b1.z; acc1[0][3] += a0*b1.w;
            acc1[1][0] += a1*b1.x; acc1[1][1] += a1*b1.y; acc1[1][2] += a1*b1.z; acc1[1][3] += a1*b1.w;
            acc3[0][0] += a0*b3.x; acc3[0][1] += a0*b3.y; acc3[0][2] += a0*b3.z; acc3[0][3] += a0*b3.w;
            acc3[1][0] += a1*b3.x; acc3[1][1] += a1*b3.y; acc3[1][2] += a1*b3.z; acc3[1][3] += a1*b3.w;
        }
        __syncthreads();
    }

    #pragma unroll
    for (int i = 0; i < 2; i++) {
        int r = row0 + ty*2 + i;
        if (r < cnt) {
            float* dst = g_hbuf + (size_t)(base + r) * F_DIM + f0 + tx*4;
            #pragma unroll
            for (int j = 0; j < 4; j++) {
                float v1 = acc1[i][j], v3 = acc3[i][j];
                dst[j] = v1 / (1.f + expf(-v1)) * v3;
            }
        }
    }
}

// ---------------------------------------------------------------------------
// Routed down-proj: dbuf[p] = gate_w[p] * (h[p] @ W2_e). grid (16, E, 32)
__global__ void __launch_bounds__(256)
down_routed_kernel(const float* __restrict__ w2) {
    int e = blockIdx.y;
    int cnt = g_count[e];
    int row0 = blockIdx.z * 32;
    if (row0 >= cnt) return;
    int base = g_offset[e];
    int d0 = blockIdx.x * 64;

    __shared__ float hs[32][36];
    __shared__ float ws[32][64];
    __shared__ float pw[32];

    int tid = threadIdx.x;
    if (tid < 32) {
        int r = row0 + tid;
        pw[tid] = (r < cnt) ? g_pair_w[base + r] : 0.f;
    }
    __syncthreads();

    int tx = tid & 15, ty = tid >> 4;
    float acc[2][4] = {};
    const float* w2e = w2 + (size_t)e * F_DIM * D_DIM;

    for (int k0 = 0; k0 < F_DIM; k0 += 32) {
        {
            int r = tid >> 3, v = tid & 7;
            float4 val = make_float4(0.f, 0.f, 0.f, 0.f);
            if (row0 + r < cnt)
                val = *(const float4*)(g_hbuf + (size_t)(base + row0 + r)*F_DIM + k0 + v*4);
            *(float4*)&hs[r][v*4] = val;
        }
        #pragma unroll
        for (int i = 0; i < 2; i++) {
            int idx = tid + i*256;
            int kr = idx >> 4, c4 = idx & 15;
            *(float4*)&ws[kr][c4*4] = *(const float4*)(w2e + (size_t)(k0+kr)*D_DIM + d0 + c4*4);
        }
        __syncthreads();
        #pragma unroll
        for (int kk = 0; kk < 32; kk++) {
            float a0 = hs[ty*2][kk], a1 = hs[ty*2+1][kk];
            float4 b = *(float4*)&ws[kk][tx*4];
            acc[0][0] += a0*b.x; acc[0][1] += a0*b.y; acc[0][2] += a0*b.z; acc[0][3] += a0*b.w;
            acc[1][0] += a1*b.x; acc[1][1] += a1*b.y; acc[1][2] += a1*b.z; acc[1][3] += a1*b.w;
        }
        __syncthreads();
    }

    #pragma unroll
    for (int i = 0; i < 2; i++) {
        int r = row0 + ty*2 + i;
        if (r < cnt) {
            float w = pw[r - row0];
            float* dst = g_dbuf + (size_t)(base + r) * D_DIM + d0 + tx*4;
            #pragma unroll
            for (int j = 0; j < 4; j++) dst[j] = w * acc[i][j];
        }
    }
}

// ---------------------------------------------------------------------------
// Shared expert up: sh = silu(x@W1s) * (x@W3s). grid (FS/64=22, 32 mtiles)
__global__ void __launch_bounds__(256)
shared_up_kernel(const float* __restrict__ x,
                 const float* __restrict__ w1,
                 const float* __restrict__ w3) {
    int row0 = blockIdx.y * 32;
    int f0 = blockIdx.x * 64;

    __shared__ float xs[32][36];
    __shared__ float w1s[32][64];
    __shared__ float w3s[32][64];

    int tid = threadIdx.x;
    int tx = tid & 15, ty = tid >> 4;
    float acc1[2][4] = {}, acc3[2][4] = {};

    for (int k0 = 0; k0 < D_DIM; k0 += 32) {
        {
            int r = tid >> 3, v = tid & 7;
            *(float4*)&xs[r][v*4] = *(const float4*)(x + (size_t)(row0 + r)*D_DIM + k0 + v*4);
        }
        #pragma unroll
        for (int i = 0; i < 2; i++) {
            int idx = tid + i*256;
            int kr = idx >> 4, c4 = idx & 15;
            *(float4*)&w1s[kr][c4*4] = *(const float4*)(w1 + (size_t)(k0+kr)*FS_DIM + f0 + c4*4);
            *(float4*)&w3s[kr][c4*4] = *(const float4*)(w3 + (size_t)(k0+kr)*FS_DIM + f0 + c4*4);
        }
        __syncthreads();
        #pragma unroll
        for (int kk = 0; kk < 32; kk++) {
            float a0 = xs[ty*2][kk], a1 = xs[ty*2+1][kk];
            float4 b1 = *(float4*)&w1s[kk][tx*4];
            float4 b3 = *(float4*)&w3s[kk][tx*4];
            acc1[0][0] += a0*b1.x; acc1[0][1] += a0*b1.y; acc1[0][2] += a0*b1.z; acc1[0][3] += a0*b1.w;
            acc1[1][0] += a1*b1.x; acc1[1][1] += a1*b1.y; acc1[1][2] += a1*b1.z; acc1[1][3] += a1*b1.w;
            acc3[0][0] += a0*b3.x; acc3[0][1] += a0*b3.y; acc3[0][2] += a0*b3.z; acc3[0][3] += a0*b3.w;
            acc3[1][0] += a1*b3.x; acc3[1][1] += a1*b3.y; acc3[1][2] += a1*b3.z; acc3[1][3] += a1*b3.w;
        }
        __syncthreads();
    }

    #pragma unroll
    for (int i = 0; i < 2; i++) {
        int t = row0 + ty*2 + i;
        float* dst = g_sh + (size_t)t * FS_DIM + f0 + tx*4;
        #pragma unroll
        for (int j = 0; j < 4; j++) {
            float v1 = acc1[i][j], v3 = acc3[i][j];
            dst[j] = v1 / (1.f + expf(-v1)) * v3;
        }
    }
}

// ---------------------------------------------------------------------------
// Shared expert down: out = sh @ W2s  (writes out directly). grid (16, 32)
__global__ void __launch_bounds__(256)
shared_down_kernel(const float* __restrict__ w2, float* __restrict__ out) {
    int row0 = blockIdx.y * 32;
    int d0 = blockIdx.x * 64;

    __shared__ float hs[32][36];
    __shared__ float ws[32][64];

    int tid = threadIdx.x;
    int tx = tid & 15, ty = tid >> 4;
    float acc[2][4] = {};

    for (int k0 = 0; k0 < FS_DIM; k0 += 32) {
        {
            int r = tid >> 3, v = tid & 7;
            *(float4*)&hs[r][v*4] = *(const float4*)(g_sh + (size_t)(row0 + r)*FS_DIM + k0 + v*4);
        }
        #pragma unroll
        for (int i = 0; i < 2; i++) {
            int idx = tid + i*256;
            int kr = idx >> 4, c4 = idx & 15;
            *(float4*)&ws[kr][c4*4] = *(const float4*)(w2 + (size_t)(k0+kr)*D_DIM + d0 + c4*4);
        }
        __syncthreads();
        #pragma unroll
        for (int kk = 0; kk < 32; kk++) {
            float a0 = hs[ty*2][kk], a1 = hs[ty*2+1][kk];
            float4 b = *(float4*)&ws[kk][tx*4];
            acc[0][0] += a0*b.x; acc[0][1] += a0*b.y; acc[0][2] += a0*b.z; acc[0][3] += a0*b.w;
            acc[1][0] += a1*b.x; acc[1][1] += a1*b.y; acc[1][2] += a1*b.z; acc[1][3] += a1*b.w;
        }
        __syncthreads();
    }

    #pragma unroll
    for (int i = 0; i < 2; i++) {
        int t = row0 + ty*2 + i;
        float* dst = out + (size_t)t * D_DIM + d0 + tx*4;
        #pragma unroll
        for (int j = 0; j < 4; j++) dst[j] = acc[i][j];
    }
}

// ---------------------------------------------------------------------------
// Combine: out[t] += sum_k dbuf[pair(t,k)]. grid 1024 blocks x 256 threads.
__global__ void combine_kernel(float* __restrict__ out) {
    int t = blockIdx.x;
    __shared__ int p[TOPK];
    if (threadIdx.x < TOPK) p[threadIdx.x] = g_tok_pair[t*TOPK + threadIdx.x];
    __syncthreads();
    int d = threadIdx.x * 4;   // 256 threads * float4 = 1024 = D_DIM
    float4 s = *(float4*)(out + (size_t)t * D_DIM + d);
    #pragma unroll
    for (int k = 0; k < TOPK; k++) {
        const float4 v = *(const float4*)(g_dbuf + (size_t)p[k] * D_DIM + d);
        s.x += v.x; s.y += v.y; s.z += v.z; s.w += v.w;
    }
    *(float4*)(out + (size_t)t * D_DIM + d) = s;
}

// ---------------------------------------------------------------------------
extern "C" void kernel_launch(void* const* d_in, const int* in_sizes, int n_in,
                              void* d_out, int out_size) {
    const float* x   = (const float*)d_in[0];
    const float* wg  = (const float*)d_in[1];
    const float* gb  = (const float*)d_in[2];
    const float* w1s = (const float*)d_in[3];
    const float* w2s = (const float*)d_in[4];
    const float* w3s = (const float*)d_in[5];
    const float* w1r = (const float*)d_in[6];
    const float* w2r = (const float*)d_in[7];
    const float* w3r = (const float*)d_in[8];
    float* out = (float*)d_out;

    // Output = concat(out [NTOK*D], scores [NTOK*E]); fall back to scratch if
    // the harness only wants the first tensor.
    float* scores;
    if (out_size >= NTOK*D_DIM + NTOK*E_NUM) {
        scores = out + (size_t)NTOK * D_DIM;
    } else {
        cudaGetSymbolAddress((void**)&scores, g_scores_scratch);
    }

    init_kernel<<<1, 64>>>();
    gate_kernel<<<NTOK, 128>>>(x, wg, gb, scores);
    scan_kernel<<<1, 32>>>();
    assign_kernel<<<4, 256>>>();

    up_routed_kernel<<<dim3(F_DIM/64, E_NUM, 32), 256>>>(x, w1r, w3r);
    down_routed_kernel<<<dim3(D_DIM/64, E_NUM, 32), 256>>>(w2r);

    shared_up_kernel<<<dim3(FS_DIM/64, NTOK/32), 256>>>(x, w1s, w3s);
    shared_down_kernel<<<dim3(D_DIM/64, NTOK/32), 256>>>(w2s, out);

    combine_kernel<<<NTOK, 256>>>(out);
}

// round 8
// speedup vs baseline: 1.4404x; 1.4404x over previous
#include <cuda_runtime.h>
#include <math.h>
#include <stdint.h>
#include <mma.h>

using namespace nvcuda;

// ---------------- problem constants ----------------
#define D_DIM   1024
#define F_DIM   704
#define E_NUM   64
#define NTOK    1024
#define TOPK    6
#define FS_DIM  1408
#define NPAIR   (NTOK*TOPK)

// ---------------- scratch (static device arrays) ----------------
__device__ float g_hbuf[NPAIR * F_DIM];
__device__ float g_dbuf[NPAIR * D_DIM];
__device__ float g_sh[NTOK * FS_DIM];
__device__ int   g_count[E_NUM];
__device__ int   g_offset[E_NUM];
__device__ int   g_cursor[E_NUM];
__device__ int   g_tok_expert[NTOK*TOPK];
__device__ float g_tok_w[NTOK*TOPK];
__device__ int   g_tok_pair[NTOK*TOPK];
__device__ int   g_pair_token[NPAIR];
__device__ float g_pair_w[NPAIR];
__device__ float g_scores_scratch[NTOK * E_NUM];

// ---------------- smem layout (floats/bytes) ----------------
// A tile: 128 x 36 (pad)  = 18432 B   at 0
// B1 tile: 32 x 68 (pad)  =  8704 B   at 18432
// B2 tile: 32 x 68 (pad)  =  8704 B   at 27136
// C tile:  128 x 68 (pad) = 34816 B   at 0 (overlaps A/B after mainloop)
// toks:    128 ints       =   512 B   at 35840
#define SA_OFF   0
#define SB1_OFF  18432
#define SB2_OFF  27136
#define SC_OFF   0
#define STOK_OFF 35840
#define SMEM_BYTES 36864
#define LDA 36
#define LDB 68
#define LDC 68

// ---------------- small kernels ----------------
__global__ void init_kernel() {
    int i = threadIdx.x;
    if (i < E_NUM) { g_count[i] = 0; g_cursor[i] = 0; }
}

__global__ void gate_kernel(const float* __restrict__ x,
                            const float* __restrict__ wg,
                            const float* __restrict__ gb,
                            float* __restrict__ scores_out) {
    __shared__ float xs[D_DIM];
    __shared__ float sc[E_NUM];
    int t = blockIdx.x;
    int tid = threadIdx.x;

    const float4* xv = (const float4*)(x + (size_t)t * D_DIM);
    float4* xsv = (float4*)xs;
    for (int i = tid; i < D_DIM/4; i += 128) xsv[i] = xv[i];
    __syncthreads();

    if (tid < E_NUM) {
        const float4* wv = (const float4*)(wg + (size_t)tid * D_DIM);
        float acc = 0.f;
        #pragma unroll 8
        for (int i = 0; i < D_DIM/4; i++) {
            float4 a = xsv[i]; float4 b = wv[i];
            acc += a.x*b.x + a.y*b.y + a.z*b.z + a.w*b.w;
        }
        float s = 1.f/(1.f + expf(-acc)) + gb[tid];
        sc[tid] = s;
        scores_out[(size_t)t * E_NUM + tid] = s;
    }
    __syncthreads();

    if (tid == 0) {
        float tmp[E_NUM];
        for (int i = 0; i < E_NUM; i++) tmp[i] = sc[i];
        int   sel[TOPK]; float selw[TOPK];
        float wsum = 0.f;
        for (int k = 0; k < TOPK; k++) {
            int bi = 0; float bv = tmp[0];
            for (int i = 1; i < E_NUM; i++)
                if (tmp[i] > bv) { bv = tmp[i]; bi = i; }
            sel[k] = bi; selw[k] = bv; wsum += bv;
            tmp[bi] = -1e30f;
        }
        float inv = 1.f / wsum;
        for (int k = 0; k < TOPK; k++) {
            int e = sel[k];
            g_tok_expert[t*TOPK + k] = e;
            g_tok_w[t*TOPK + k] = selw[k] * inv;
            atomicAdd(&g_count[e], 1);
        }
    }
}

__global__ void scan_kernel() {
    if (threadIdx.x == 0) {
        int acc = 0;
        for (int e = 0; e < E_NUM; e++) { g_offset[e] = acc; acc += g_count[e]; }
    }
}

__global__ void assign_kernel() {
    int t = blockIdx.x * blockDim.x + threadIdx.x;
    if (t >= NTOK) return;
    for (int k = 0; k < TOPK; k++) {
        int e = g_tok_expert[t*TOPK + k];
        int slot = atomicAdd(&g_cursor[e], 1);
        int p = g_offset[e] + slot;
        g_pair_token[p] = t;
        g_pair_w[p] = g_tok_w[t*TOPK + k];
        g_tok_pair[t*TOPK + k] = p;
    }
}

// ---------------- WMMA tf32 helpers ----------------
using FragA = wmma::fragment<wmma::matrix_a, 16, 16, 8, wmma::precision::tf32, wmma::row_major>;
using FragB = wmma::fragment<wmma::matrix_b, 16, 16, 8, wmma::precision::tf32, wmma::row_major>;
using FragC = wmma::fragment<wmma::accumulator, 16, 16, 8, float>;

__device__ __forceinline__ void cvt_a(FragA& f) {
    #pragma unroll
    for (int i = 0; i < f.num_elements; i++) f.x[i] = wmma::__float_to_tf32(f.x[i]);
}
__device__ __forceinline__ void cvt_b(FragB& f) {
    #pragma unroll
    for (int i = 0; i < f.num_elements; i++) f.x[i] = wmma::__float_to_tf32(f.x[i]);
}

// Load one K-chunk of B into smem: 32 rows x 64 cols from B + (k0+row)*ldB + f0
__device__ __forceinline__ void load_b_tile(float* Bs, const float* __restrict__ B,
                                            int ldB, int k0, int f0, int tid) {
    #pragma unroll
    for (int i = 0; i < 2; i++) {
        int lin = tid + i * 256;
        int row = lin >> 4, c4 = lin & 15;
        float4 v = *(const float4*)(B + (size_t)(k0 + row) * ldB + f0 + c4 * 4);
        *(float4*)(Bs + row * LDB + c4 * 4) = v;
    }
}

// Load A chunk: 128 rows x 32 cols; per-thread row pointers precomputed.
__device__ __forceinline__ void load_a_tile(float* As, const float4* const ar[4],
                                            int k0, int tid) {
    int c4 = tid & 7;
    #pragma unroll
    for (int i = 0; i < 4; i++) {
        int row = (tid >> 3) + i * 32;
        float4 v = ar[i][(k0 >> 2) + c4];
        *(float4*)(As + row * LDA + c4 * 4) = v;
    }
}

// ---------------- routed up-proj ----------------
// h[p, f0:f0+64] = silu(x@W1_e) * (x@W3_e)   (gate weight applied in combine)
__global__ void __launch_bounds__(256)
up_tc(const float* __restrict__ x,
      const float* __restrict__ w1,
      const float* __restrict__ w3) {
    int e = blockIdx.y;
    int cnt = g_count[e];
    int row0 = blockIdx.z * 128;
    if (row0 >= cnt) return;
    int base = g_offset[e];
    int f0 = blockIdx.x * 64;
    extern __shared__ float sm[];
    float* As = sm;                                  // SA_OFF
    float* B1s = (float*)((char*)sm + SB1_OFF);
    float* B2s = (float*)((char*)sm + SB2_OFF);
    float* Cs = (float*)((char*)sm + SC_OFF);
    int*   toks = (int*)((char*)sm + STOK_OFF);

    int tid = threadIdx.x;
    int wid = tid >> 5;
    int warpM = wid >> 1, warpN = wid & 1;           // 4 x 2

    if (tid < 128) {
        int r = row0 + tid;
        toks[tid] = (r < cnt) ? g_pair_token[base + r] : 0;
    }
    __syncthreads();

    const float4* ar[4];
    #pragma unroll
    for (int i = 0; i < 4; i++)
        ar[i] = (const float4*)(x + (size_t)toks[(tid >> 3) + i * 32] * D_DIM);

    const float* B1 = w1 + (size_t)e * D_DIM * F_DIM;
    const float* B2 = w3 + (size_t)e * D_DIM * F_DIM;

    FragC c1[2][2], c3[2][2];
    #pragma unroll
    for (int mi = 0; mi < 2; mi++)
        #pragma unroll
        for (int ni = 0; ni < 2; ni++) {
            wmma::fill_fragment(c1[mi][ni], 0.f);
            wmma::fill_fragment(c3[mi][ni], 0.f);
        }

    for (int k0 = 0; k0 < D_DIM; k0 += 32) {
        load_a_tile(As, ar, k0, tid);
        load_b_tile(B1s, B1, F_DIM, k0, f0, tid);
        load_b_tile(B2s, B2, F_DIM, k0, f0, tid);
        __syncthreads();
        #pragma unroll
        for (int ks = 0; ks < 4; ks++) {
            FragA a[2];
            #pragma unroll
            for (int mi = 0; mi < 2; mi++) {
                wmma::load_matrix_sync(a[mi], As + (warpM*32 + mi*16) * LDA + ks*8, LDA);
                cvt_a(a[mi]);
            }
            FragB b;
            #pragma unroll
            for (int ni = 0; ni < 2; ni++) {
                wmma::load_matrix_sync(b, B1s + (ks*8) * LDB + warpN*32 + ni*16, LDB);
                cvt_b(b);
                #pragma unroll
                for (int mi = 0; mi < 2; mi++)
                    wmma::mma_sync(c1[mi][ni], a[mi], b, c1[mi][ni]);
                wmma::load_matrix_sync(b, B2s + (ks*8) * LDB + warpN*32 + ni*16, LDB);
                cvt_b(b);
                #pragma unroll
                for (int mi = 0; mi < 2; mi++)
                    wmma::mma_sync(c3[mi][ni], a[mi], b, c3[mi][ni]);
            }
        }
        __syncthreads();
    }

    // elementwise silu(c1)*c3 on matching fragments, then smem C + masked copy
    #pragma unroll
    for (int mi = 0; mi < 2; mi++)
        #pragma unroll
        for (int ni = 0; ni < 2; ni++) {
            #pragma unroll
            for (int k = 0; k < c1[mi][ni].num_elements; k++) {
                float v1 = c1[mi][ni].x[k], v3 = c3[mi][ni].x[k];
                c1[mi][ni].x[k] = v1 / (1.f + expf(-v1)) * v3;
            }
            wmma::store_matrix_sync(Cs + (warpM*32 + mi*16) * LDC + warpN*32 + ni*16,
                                    c1[mi][ni], LDC, wmma::mem_row_major);
        }
    __syncthreads();

    int valid = cnt - row0; if (valid > 128) valid = 128;
    #pragma unroll
    for (int i = 0; i < 8; i++) {
        int lin = tid + i * 256;
        int row = lin >> 4, c4 = lin & 15;
        if (row < valid) {
            float4 v = *(float4*)(Cs + row * LDC + c4 * 4);
            *(float4*)(g_hbuf + (size_t)(base + row0 + row) * F_DIM + f0 + c4 * 4) = v;
        }
    }
}

// ---------------- routed down-proj ----------------
// dbuf[p, d0:d0+64] = h[p] @ W2_e
__global__ void __launch_bounds__(256)
down_tc(const float* __restrict__ w2) {
    int e = blockIdx.y;
    int cnt = g_count[e];
    int row0 = blockIdx.z * 128;
    if (row0 >= cnt) return;
    int base = g_offset[e];
    int d0 = blockIdx.x * 64;
    extern __shared__ float sm[];
    float* As = sm;
    float* B1s = (float*)((char*)sm + SB1_OFF);
    float* Cs = (float*)((char*)sm + SC_OFF);

    int tid = threadIdx.x;
    int wid = tid >> 5;
    int warpM = wid >> 1, warpN = wid & 1;

    const float4* ar[4];
    #pragma unroll
    for (int i = 0; i < 4; i++) {
        int r = row0 + (tid >> 3) + i * 32;
        int rr = (r < cnt) ? r : (cnt - 1);
        ar[i] = (const float4*)(g_hbuf + (size_t)(base + rr) * F_DIM);
    }
    const float* B1 = w2 + (size_t)e * F_DIM * D_DIM;

    FragC c[2][2];
    #pragma unroll
    for (int mi = 0; mi < 2; mi++)
        #pragma unroll
        for (int ni = 0; ni < 2; ni++)
            wmma::fill_fragment(c[mi][ni], 0.f);

    for (int k0 = 0; k0 < F_DIM; k0 += 32) {
        load_a_tile(As, ar, k0, tid);
        load_b_tile(B1s, B1, D_DIM, k0, d0, tid);
        __syncthreads();
        #pragma unroll
        for (int ks = 0; ks < 4; ks++) {
            FragA a[2];
            #pragma unroll
            for (int mi = 0; mi < 2; mi++) {
                wmma::load_matrix_sync(a[mi], As + (warpM*32 + mi*16) * LDA + ks*8, LDA);
                cvt_a(a[mi]);
            }
            #pragma unroll
            for (int ni = 0; ni < 2; ni++) {
                FragB b;
                wmma::load_matrix_sync(b, B1s + (ks*8) * LDB + warpN*32 + ni*16, LDB);
                cvt_b(b);
                #pragma unroll
                for (int mi = 0; mi < 2; mi++)
                    wmma::mma_sync(c[mi][ni], a[mi], b, c[mi][ni]);
            }
        }
        __syncthreads();
    }

    #pragma unroll
    for (int mi = 0; mi < 2; mi++)
        #pragma unroll
        for (int ni = 0; ni < 2; ni++)
            wmma::store_matrix_sync(Cs + (warpM*32 + mi*16) * LDC + warpN*32 + ni*16,
                                    c[mi][ni], LDC, wmma::mem_row_major);
    __syncthreads();

    int valid = cnt - row0; if (valid > 128) valid = 128;
    #pragma unroll
    for (int i = 0; i < 8; i++) {
        int lin = tid + i * 256;
        int row = lin >> 4, c4 = lin & 15;
        if (row < valid) {
            float4 v = *(float4*)(Cs + row * LDC + c4 * 4);
            *(float4*)(g_dbuf + (size_t)(base + row0 + row) * D_DIM + d0 + c4 * 4) = v;
        }
    }
}

// ---------------- shared expert up ----------------
__global__ void __launch_bounds__(256)
shared_up_tc(const float* __restrict__ x,
             const float* __restrict__ w1,
             const float* __restrict__ w3) {
    int row0 = blockIdx.y * 128;
    int f0 = blockIdx.x * 64;
    extern __shared__ float sm[];
    float* As = sm;
    float* B1s = (float*)((char*)sm + SB1_OFF);
    float* B2s = (float*)((char*)sm + SB2_OFF);

    int tid = threadIdx.x;
    int wid = tid >> 5;
    int warpM = wid >> 1, warpN = wid & 1;

    const float4* ar[4];
    #pragma unroll
    for (int i = 0; i < 4; i++)
        ar[i] = (const float4*)(x + (size_t)(row0 + (tid >> 3) + i * 32) * D_DIM);

    FragC c1[2][2], c3[2][2];
    #pragma unroll
    for (int mi = 0; mi < 2; mi++)
        #pragma unroll
        for (int ni = 0; ni < 2; ni++) {
            wmma::fill_fragment(c1[mi][ni], 0.f);
            wmma::fill_fragment(c3[mi][ni], 0.f);
        }

    for (int k0 = 0; k0 < D_DIM; k0 += 32) {
        load_a_tile(As, ar, k0, tid);
        load_b_tile(B1s, w1, FS_DIM, k0, f0, tid);
        load_b_tile(B2s, w3, FS_DIM, k0, f0, tid);
        __syncthreads();
        #pragma unroll
        for (int ks = 0; ks < 4; ks++) {
            FragA a[2];
            #pragma unroll
            for (int mi = 0; mi < 2; mi++) {
                wmma::load_matrix_sync(a[mi], As + (warpM*32 + mi*16) * LDA + ks*8, LDA);
                cvt_a(a[mi]);
            }
            FragB b;
            #pragma unroll
            for (int ni = 0; ni < 2; ni++) {
                wmma::load_matrix_sync(b, B1s + (ks*8) * LDB + warpN*32 + ni*16, LDB);
                cvt_b(b);
                #pragma unroll
                for (int mi = 0; mi < 2; mi++)
                    wmma::mma_sync(c1[mi][ni], a[mi], b, c1[mi][ni]);
                wmma::load_matrix_sync(b, B2s + (ks*8) * LDB + warpN*32 + ni*16, LDB);
                cvt_b(b);
                #pragma unroll
                for (int mi = 0; mi < 2; mi++)
                    wmma::mma_sync(c3[mi][ni], a[mi], b, c3[mi][ni]);
            }
        }
        __syncthreads();
    }

    #pragma unroll
    for (int mi = 0; mi < 2; mi++)
        #pragma unroll
        for (int ni = 0; ni < 2; ni++) {
            #pragma unroll
            for (int k = 0; k < c1[mi][ni].num_elements; k++) {
                float v1 = c1[mi][ni].x[k], v3 = c3[mi][ni].x[k];
                c1[mi][ni].x[k] = v1 / (1.f + expf(-v1)) * v3;
            }
            wmma::store_matrix_sync(
                g_sh + (size_t)(row0 + warpM*32 + mi*16) * FS_DIM + f0 + warpN*32 + ni*16,
                c1[mi][ni], FS_DIM, wmma::mem_row_major);
        }
}

// ---------------- shared expert down ----------------
__global__ void __launch_bounds__(256)
shared_down_tc(const float* __restrict__ w2, float* __restrict__ out) {
    int row0 = blockIdx.y * 128;
    int d0 = blockIdx.x * 64;
    extern __shared__ float sm[];
    float* As = sm;
    float* B1s = (float*)((char*)sm + SB1_OFF);

    int tid = threadIdx.x;
    int wid = tid >> 5;
    int warpM = wid >> 1, warpN = wid & 1;

    const float4* ar[4];
    #pragma unroll
    for (int i = 0; i < 4; i++)
        ar[i] = (const float4*)(g_sh + (size_t)(row0 + (tid >> 3) + i * 32) * FS_DIM);

    FragC c[2][2];
    #pragma unroll
    for (int mi = 0; mi < 2; mi++)
        #pragma unroll
        for (int ni = 0; ni < 2; ni++)
            wmma::fill_fragment(c[mi][ni], 0.f);

    for (int k0 = 0; k0 < FS_DIM; k0 += 32) {
        load_a_tile(As, ar, k0, tid);
        load_b_tile(B1s, w2, D_DIM, k0, d0, tid);
        __syncthreads();
        #pragma unroll
        for (int ks = 0; ks < 4; ks++) {
            FragA a[2];
            #pragma unroll
            for (int mi = 0; mi < 2; mi++) {
                wmma::load_matrix_sync(a[mi], As + (warpM*32 + mi*16) * LDA + ks*8, LDA);
                cvt_a(a[mi]);
            }
            #pragma unroll
            for (int ni = 0; ni < 2; ni++) {
                FragB b;
                wmma::load_matrix_sync(b, B1s + (ks*8) * LDB + warpN*32 + ni*16, LDB);
                cvt_b(b);
                #pragma unroll
                for (int mi = 0; mi < 2; mi++)
                    wmma::mma_sync(c[mi][ni], a[mi], b, c[mi][ni]);
            }
        }
        __syncthreads();
    }

    #pragma unroll
    for (int mi = 0; mi < 2; mi++)
        #pragma unroll
        for (int ni = 0; ni < 2; ni++)
            wmma::store_matrix_sync(
                out + (size_t)(row0 + warpM*32 + mi*16) * D_DIM + d0 + warpN*32 + ni*16,
                c[mi][ni], D_DIM, wmma::mem_row_major);
}

// ---------------- combine (applies gate weights) ----------------
__global__ void combine_kernel(float* __restrict__ out) {
    int t = blockIdx.x;
    __shared__ int p[TOPK];
    __shared__ float w[TOPK];
    if (threadIdx.x < TOPK) {
        p[threadIdx.x] = g_tok_pair[t*TOPK + threadIdx.x];
        w[threadIdx.x] = g_tok_w[t*TOPK + threadIdx.x];
    }
    __syncthreads();
    int d = threadIdx.x * 4;
    float4 s = *(float4*)(out + (size_t)t * D_DIM + d);
    #pragma unroll
    for (int k = 0; k < TOPK; k++) {
        const float4 v = *(const float4*)(g_dbuf + (size_t)p[k] * D_DIM + d);
        float wk = w[k];
        s.x += wk*v.x; s.y += wk*v.y; s.z += wk*v.z; s.w += wk*v.w;
    }
    *(float4*)(out + (size_t)t * D_DIM + d) = s;
}

// ---------------------------------------------------------------------------
extern "C" void kernel_launch(void* const* d_in, const int* in_sizes, int n_in,
                              void* d_out, int out_size) {
    const float* x   = (const float*)d_in[0];
    const float* wg  = (const float*)d_in[1];
    const float* gb  = (const float*)d_in[2];
    const float* w1s = (const float*)d_in[3];
    const float* w2s = (const float*)d_in[4];
    const float* w3s = (const float*)d_in[5];
    const float* w1r = (const float*)d_in[6];
    const float* w2r = (const float*)d_in[7];
    const float* w3r = (const float*)d_in[8];
    float* out = (float*)d_out;

    float* scores;
    if (out_size >= NTOK*D_DIM + NTOK*E_NUM) {
        scores = out + (size_t)NTOK * D_DIM;
    } else {
        cudaGetSymbolAddress((void**)&scores, g_scores_scratch);
    }

    init_kernel<<<1, 64>>>();
    gate_kernel<<<NTOK, 128>>>(x, wg, gb, scores);
    scan_kernel<<<1, 32>>>();
    assign_kernel<<<4, 256>>>();

    up_tc<<<dim3(F_DIM/64, E_NUM, 8), 256, SMEM_BYTES>>>(x, w1r, w3r);
    down_tc<<<dim3(D_DIM/64, E_NUM, 8), 256, SMEM_BYTES>>>(w2r);

    shared_up_tc<<<dim3(FS_DIM/64, NTOK/128), 256, SMEM_BYTES>>>(x, w1s, w3s);
    shared_down_tc<<<dim3(D_DIM/64, NTOK/128), 256, SMEM_BYTES>>>(w2s, out);

    combine_kernel<<<NTOK, 256>>>(out);
}

// round 9
// speedup vs baseline: 1.7647x; 1.2251x over previous
#include <cuda_runtime.h>
#include <math.h>
#include <stdint.h>
#include <mma.h>

using namespace nvcuda;

// ---------------- problem constants ----------------
#define D_DIM   1024
#define F_DIM   704
#define E_NUM   64
#define NTOK    1024
#define TOPK    6
#define FS_DIM  1408
#define NPAIR   (NTOK*TOPK)

// ---------------- scratch (static device arrays) ----------------
__device__ float g_hbuf[NPAIR * F_DIM];
__device__ float g_dbuf[NPAIR * D_DIM];
__device__ float g_sh[NTOK * FS_DIM];
__device__ int   g_count[E_NUM];
__device__ int   g_offset[E_NUM];
__device__ int   g_cursor[E_NUM];
__device__ int   g_tok_expert[NTOK*TOPK];
__device__ float g_tok_w[NTOK*TOPK];
__device__ int   g_tok_pair[NTOK*TOPK];
__device__ int   g_pair_token[NPAIR];
__device__ float g_pair_w[NPAIR];
__device__ float g_scores_scratch[NTOK * E_NUM];

// ---------------- smem layout (float offsets) ----------------
#define LDA 36
#define LDB 68
#define LDC 68
#define SA0    0
#define SA1    4608
#define SB1_0  9216
#define SB1_1  11392
#define SB2_0  13568
#define SB2_1  15744
#define STOK2  17920
#define SMEM2_BYTES 72192          // 2-matrix kernel (up)
#define STOK1  13568
#define SMEM1_BYTES 54784          // 1-matrix kernel (down)

// ---------------- cp.async helpers ----------------
__device__ __forceinline__ void cp16(uint32_t s, const void* g) {
    asm volatile("cp.async.cg.shared.global [%0], [%1], 16;" :: "r"(s), "l"(g));
}
__device__ __forceinline__ void cp_commit() {
    asm volatile("cp.async.commit_group;" ::: "memory");
}
template<int N> __device__ __forceinline__ void cp_wait() {
    asm volatile("cp.async.wait_group %0;" :: "n"(N) : "memory");
}

// ---------------- WMMA tf32 helpers ----------------
using FragA = wmma::fragment<wmma::matrix_a, 16, 16, 8, wmma::precision::tf32, wmma::row_major>;
using FragB = wmma::fragment<wmma::matrix_b, 16, 16, 8, wmma::precision::tf32, wmma::row_major>;
using FragC = wmma::fragment<wmma::accumulator, 16, 16, 8, float>;

__device__ __forceinline__ void cvt_a(FragA& f) {
    #pragma unroll
    for (int i = 0; i < f.num_elements; i++) f.x[i] = wmma::__float_to_tf32(f.x[i]);
}
__device__ __forceinline__ void cvt_b(FragB& f) {
    #pragma unroll
    for (int i = 0; i < f.num_elements; i++) f.x[i] = wmma::__float_to_tf32(f.x[i]);
}

// ---------------- small kernels ----------------
__global__ void init_kernel() {
    int i = threadIdx.x;
    if (i < E_NUM) { g_count[i] = 0; g_cursor[i] = 0; }
}

__global__ void gate_kernel(const float* __restrict__ x,
                            const float* __restrict__ wg,
                            const float* __restrict__ gb,
                            float* __restrict__ scores_out) {
    __shared__ float xs[D_DIM];
    __shared__ float sc[E_NUM];
    int t = blockIdx.x;
    int tid = threadIdx.x;

    const float4* xv = (const float4*)(x + (size_t)t * D_DIM);
    float4* xsv = (float4*)xs;
    for (int i = tid; i < D_DIM/4; i += 128) xsv[i] = xv[i];
    __syncthreads();

    if (tid < E_NUM) {
        const float4* wv = (const float4*)(wg + (size_t)tid * D_DIM);
        float acc = 0.f;
        #pragma unroll 8
        for (int i = 0; i < D_DIM/4; i++) {
            float4 a = xsv[i]; float4 b = wv[i];
            acc += a.x*b.x + a.y*b.y + a.z*b.z + a.w*b.w;
        }
        float s = 1.f/(1.f + expf(-acc)) + gb[tid];
        sc[tid] = s;
        scores_out[(size_t)t * E_NUM + tid] = s;
    }
    __syncthreads();

    if (tid == 0) {
        float tmp[E_NUM];
        for (int i = 0; i < E_NUM; i++) tmp[i] = sc[i];
        int   sel[TOPK]; float selw[TOPK];
        float wsum = 0.f;
        for (int k = 0; k < TOPK; k++) {
            int bi = 0; float bv = tmp[0];
            for (int i = 1; i < E_NUM; i++)
                if (tmp[i] > bv) { bv = tmp[i]; bi = i; }
            sel[k] = bi; selw[k] = bv; wsum += bv;
            tmp[bi] = -1e30f;
        }
        float inv = 1.f / wsum;
        for (int k = 0; k < TOPK; k++) {
            int e = sel[k];
            g_tok_expert[t*TOPK + k] = e;
            g_tok_w[t*TOPK + k] = selw[k] * inv;
            atomicAdd(&g_count[e], 1);
        }
    }
}

__global__ void scan_kernel() {
    if (threadIdx.x == 0) {
        int acc = 0;
        for (int e = 0; e < E_NUM; e++) { g_offset[e] = acc; acc += g_count[e]; }
    }
}

__global__ void assign_kernel() {
    int t = blockIdx.x * blockDim.x + threadIdx.x;
    if (t >= NTOK) return;
    for (int k = 0; k < TOPK; k++) {
        int e = g_tok_expert[t*TOPK + k];
        int slot = atomicAdd(&g_cursor[e], 1);
        int p = g_offset[e] + slot;
        g_pair_token[p] = t;
        g_pair_w[p] = g_tok_w[t*TOPK + k];
        g_tok_pair[t*TOPK + k] = p;
    }
}

// ===========================================================================
// Fused up-proj: routed experts (y<64) and shared expert (y==64).
// C = silu(A@B1) * (A@B3); routed -> g_hbuf (masked), shared -> g_sh.
// K = D_DIM for both. grid (22, 65, 8), 256 threads.
// ===========================================================================
__global__ void __launch_bounds__(256)
up_fused(const float* __restrict__ x,
         const float* __restrict__ w1r,
         const float* __restrict__ w3r,
         const float* __restrict__ w1s,
         const float* __restrict__ w3s) {
    extern __shared__ float sm[];
    const int tid = threadIdx.x;
    const int y = blockIdx.y;
    const bool se = (y == E_NUM);
    const int f0 = blockIdx.x * 64;
    const int row0 = blockIdx.z * 128;

    int cnt, base, ldB, ldD;
    const float *B1, *B2;
    float* dstbuf;
    if (se) {
        cnt = NTOK; base = 0;
        B1 = w1s; B2 = w3s; ldB = FS_DIM;
        dstbuf = g_sh; ldD = FS_DIM;
    } else {
        if (f0 >= F_DIM) return;
        cnt = g_count[y];
        if (row0 >= cnt) return;
        base = g_offset[y];
        B1 = w1r + (size_t)y * D_DIM * F_DIM;
        B2 = w3r + (size_t)y * D_DIM * F_DIM;
        ldB = F_DIM;
        dstbuf = g_hbuf; ldD = F_DIM;
    }

    int* toks = (int*)(sm + STOK2);
    if (tid < 128) {
        int r = row0 + tid;
        if (se) toks[tid] = r;
        else    toks[tid] = (r < cnt) ? g_pair_token[base + r] : 0;
    }
    __syncthreads();

    // per-thread load geometry
    const int c4a = tid & 7;             // A: 16B column
    const int arow = tid >> 3;           // A: base row (4 rows, +32 apart)
    const int bc4 = tid & 15;            // B: 16B column
    const int brow = tid >> 4;           // B: base row (2 rows, +16 apart)

    const float4* ar[4];
    uint32_t a_off[4];
    #pragma unroll
    for (int i = 0; i < 4; i++) {
        ar[i] = (const float4*)(x + (size_t)toks[arow + i*32] * D_DIM);
        a_off[i] = (uint32_t)(((arow + i*32) * LDA + c4a*4) * 4);
    }
    uint32_t b_off[2];
    #pragma unroll
    for (int i = 0; i < 2; i++)
        b_off[i] = (uint32_t)(((brow + i*16) * LDB + bc4*4) * 4);

    uint32_t sbase = (uint32_t)__cvta_generic_to_shared(sm);

    const int wid = tid >> 5;
    const int warpM = wid >> 1, warpN = wid & 1;

    FragC c1[2][2], c3[2][2];
    #pragma unroll
    for (int mi = 0; mi < 2; mi++)
        #pragma unroll
        for (int ni = 0; ni < 2; ni++) {
            wmma::fill_fragment(c1[mi][ni], 0.f);
            wmma::fill_fragment(c3[mi][ni], 0.f);
        }

    const int nchunk = D_DIM / 32;

    // issue one chunk's cp.async group
    #define ISSUE_UP(kc) do { \
        const int k0_ = (kc) * 32; \
        const int b_ = (kc) & 1; \
        uint32_t sa_ = sbase + (b_ ? SA1*4 : SA0*4); \
        _Pragma("unroll") \
        for (int i_ = 0; i_ < 4; i_++) \
            cp16(sa_ + a_off[i_], ar[i_] + (k0_ >> 2) + c4a); \
        uint32_t sb1_ = sbase + (b_ ? SB1_1*4 : SB1_0*4); \
        uint32_t sb2_ = sbase + (b_ ? SB2_1*4 : SB2_0*4); \
        _Pragma("unroll") \
        for (int i_ = 0; i_ < 2; i_++) { \
            cp16(sb1_ + b_off[i_], B1 + (size_t)(k0_ + brow + i_*16) * ldB + f0 + bc4*4); \
            cp16(sb2_ + b_off[i_], B2 + (size_t)(k0_ + brow + i_*16) * ldB + f0 + bc4*4); \
        } \
        cp_commit(); \
    } while (0)

    ISSUE_UP(0);
    for (int kc = 0; kc < nchunk; kc++) {
        if (kc + 1 < nchunk) { ISSUE_UP(kc + 1); cp_wait<1>(); }
        else                 { cp_wait<0>(); }
        __syncthreads();
        const float* As  = sm + ((kc & 1) ? SA1 : SA0);
        const float* B1s = sm + ((kc & 1) ? SB1_1 : SB1_0);
        const float* B2s = sm + ((kc & 1) ? SB2_1 : SB2_0);
        #pragma unroll
        for (int ks = 0; ks < 4; ks++) {
            FragA a[2];
            #pragma unroll
            for (int mi = 0; mi < 2; mi++) {
                wmma::load_matrix_sync(a[mi], As + (warpM*32 + mi*16) * LDA + ks*8, LDA);
                cvt_a(a[mi]);
            }
            FragB b;
            #pragma unroll
            for (int ni = 0; ni < 2; ni++) {
                wmma::load_matrix_sync(b, B1s + (ks*8) * LDB + warpN*32 + ni*16, LDB);
                cvt_b(b);
                #pragma unroll
                for (int mi = 0; mi < 2; mi++)
                    wmma::mma_sync(c1[mi][ni], a[mi], b, c1[mi][ni]);
                wmma::load_matrix_sync(b, B2s + (ks*8) * LDB + warpN*32 + ni*16, LDB);
                cvt_b(b);
                #pragma unroll
                for (int mi = 0; mi < 2; mi++)
                    wmma::mma_sync(c3[mi][ni], a[mi], b, c3[mi][ni]);
            }
        }
        __syncthreads();
    }
    #undef ISSUE_UP

    // epilogue: silu(c1)*c3 -> smem C -> masked copy
    float* Cs = sm;
    #pragma unroll
    for (int mi = 0; mi < 2; mi++)
        #pragma unroll
        for (int ni = 0; ni < 2; ni++) {
            #pragma unroll
            for (int k = 0; k < c1[mi][ni].num_elements; k++) {
                float v1 = c1[mi][ni].x[k], v3 = c3[mi][ni].x[k];
                c1[mi][ni].x[k] = v1 / (1.f + expf(-v1)) * v3;
            }
            wmma::store_matrix_sync(Cs + (warpM*32 + mi*16) * LDC + warpN*32 + ni*16,
                                    c1[mi][ni], LDC, wmma::mem_row_major);
        }
    __syncthreads();

    int valid = cnt - row0; if (valid > 128) valid = 128;
    #pragma unroll
    for (int i = 0; i < 8; i++) {
        int lin = tid + i * 256;
        int row = lin >> 4, cc = lin & 15;
        if (row < valid) {
            float4 v = *(float4*)(Cs + row * LDC + cc * 4);
            *(float4*)(dstbuf + (size_t)(base + row0 + row) * ldD + f0 + cc * 4) = v;
        }
    }
}

// ===========================================================================
// Fused down-proj: routed (y<64, A=g_hbuf, K=F_DIM, dst=g_dbuf)
//                  shared (y==64, A=g_sh, K=FS_DIM, dst=out).
// grid (16, 65, 8), 256 threads.
// ===========================================================================
__global__ void __launch_bounds__(256)
down_fused(const float* __restrict__ w2r,
           const float* __restrict__ w2s,
           float* __restrict__ out) {
    extern __shared__ float sm[];
    const int tid = threadIdx.x;
    const int y = blockIdx.y;
    const bool se = (y == E_NUM);
    const int d0 = blockIdx.x * 64;
    const int row0 = blockIdx.z * 128;

    int cnt, base, nchunk;
    const float* B1;
    const float* Abase;
    int ldA;
    float* dstbuf;
    if (se) {
        cnt = NTOK; base = 0;
        B1 = w2s; nchunk = FS_DIM / 32;
        Abase = g_sh; ldA = FS_DIM;
        dstbuf = out;
    } else {
        cnt = g_count[y];
        if (row0 >= cnt) return;
        base = g_offset[y];
        B1 = w2r + (size_t)y * F_DIM * D_DIM;
        nchunk = F_DIM / 32;
        Abase = g_hbuf; ldA = F_DIM;
        dstbuf = g_dbuf;
    }

    const int c4a = tid & 7;
    const int arow = tid >> 3;
    const int bc4 = tid & 15;
    const int brow = tid >> 4;

    const float4* ar[4];
    uint32_t a_off[4];
    #pragma unroll
    for (int i = 0; i < 4; i++) {
        int r = row0 + arow + i*32;
        int rr = (r < cnt) ? r : (cnt - 1);
        ar[i] = (const float4*)(Abase + (size_t)(base + rr) * ldA);
        a_off[i] = (uint32_t)(((arow + i*32) * LDA + c4a*4) * 4);
    }
    uint32_t b_off[2];
    #pragma unroll
    for (int i = 0; i < 2; i++)
        b_off[i] = (uint32_t)(((brow + i*16) * LDB + bc4*4) * 4);

    uint32_t sbase = (uint32_t)__cvta_generic_to_shared(sm);

    const int wid = tid >> 5;
    const int warpM = wid >> 1, warpN = wid & 1;

    FragC c[2][2];
    #pragma unroll
    for (int mi = 0; mi < 2; mi++)
        #pragma unroll
        for (int ni = 0; ni < 2; ni++)
            wmma::fill_fragment(c[mi][ni], 0.f);

    #define ISSUE_DN(kc) do { \
        const int k0_ = (kc) * 32; \
        const int b_ = (kc) & 1; \
        uint32_t sa_ = sbase + (b_ ? SA1*4 : SA0*4); \
        _Pragma("unroll") \
        for (int i_ = 0; i_ < 4; i_++) \
            cp16(sa_ + a_off[i_], ar[i_] + (k0_ >> 2) + c4a); \
        uint32_t sb1_ = sbase + (b_ ? SB1_1*4 : SB1_0*4); \
        _Pragma("unroll") \
        for (int i_ = 0; i_ < 2; i_++) \
            cp16(sb1_ + b_off[i_], B1 + (size_t)(k0_ + brow + i_*16) * D_DIM + d0 + bc4*4); \
        cp_commit(); \
    } while (0)

    ISSUE_DN(0);
    for (int kc = 0; kc < nchunk; kc++) {
        if (kc + 1 < nchunk) { ISSUE_DN(kc + 1); cp_wait<1>(); }
        else                 { cp_wait<0>(); }
        __syncthreads();
        const float* As  = sm + ((kc & 1) ? SA1 : SA0);
        const float* B1s = sm + ((kc & 1) ? SB1_1 : SB1_0);
        #pragma unroll
        for (int ks = 0; ks < 4; ks++) {
            FragA a[2];
            #pragma unroll
            for (int mi = 0; mi < 2; mi++) {
                wmma::load_matrix_sync(a[mi], As + (warpM*32 + mi*16) * LDA + ks*8, LDA);
                cvt_a(a[mi]);
            }
            #pragma unroll
            for (int ni = 0; ni < 2; ni++) {
                FragB b;
                wmma::load_matrix_sync(b, B1s + (ks*8) * LDB + warpN*32 + ni*16, LDB);
                cvt_b(b);
                #pragma unroll
                for (int mi = 0; mi < 2; mi++)
                    wmma::mma_sync(c[mi][ni], a[mi], b, c[mi][ni]);
            }
        }
        __syncthreads();
    }
    #undef ISSUE_DN

    float* Cs = sm;
    #pragma unroll
    for (int mi = 0; mi < 2; mi++)
        #pragma unroll
        for (int ni = 0; ni < 2; ni++)
            wmma::store_matrix_sync(Cs + (warpM*32 + mi*16) * LDC + warpN*32 + ni*16,
                                    c[mi][ni], LDC, wmma::mem_row_major);
    __syncthreads();

    int valid = cnt - row0; if (valid > 128) valid = 128;
    const int ldD = D_DIM;
    #pragma unroll
    for (int i = 0; i < 8; i++) {
        int lin = tid + i * 256;
        int row = lin >> 4, cc = lin & 15;
        if (row < valid) {
            float4 v = *(float4*)(Cs + row * LDC + cc * 4);
            *(float4*)(dstbuf + (size_t)(base + row0 + row) * ldD + d0 + cc * 4) = v;
        }
    }
}

// ---------------- combine (applies gate weights) ----------------
__global__ void combine_kernel(float* __restrict__ out) {
    int t = blockIdx.x;
    __shared__ int p[TOPK];
    __shared__ float w[TOPK];
    if (threadIdx.x < TOPK) {
        p[threadIdx.x] = g_tok_pair[t*TOPK + threadIdx.x];
        w[threadIdx.x] = g_tok_w[t*TOPK + threadIdx.x];
    }
    __syncthreads();
    int d = threadIdx.x * 4;
    float4 s = *(float4*)(out + (size_t)t * D_DIM + d);
    #pragma unroll
    for (int k = 0; k < TOPK; k++) {
        const float4 v = *(const float4*)(g_dbuf + (size_t)p[k] * D_DIM + d);
        float wk = w[k];
        s.x += wk*v.x; s.y += wk*v.y; s.z += wk*v.z; s.w += wk*v.w;
    }
    *(float4*)(out + (size_t)t * D_DIM + d) = s;
}

// ---------------------------------------------------------------------------
extern "C" void kernel_launch(void* const* d_in, const int* in_sizes, int n_in,
                              void* d_out, int out_size) {
    const float* x   = (const float*)d_in[0];
    const float* wg  = (const float*)d_in[1];
    const float* gb  = (const float*)d_in[2];
    const float* w1s = (const float*)d_in[3];
    const float* w2s = (const float*)d_in[4];
    const float* w3s = (const float*)d_in[5];
    const float* w1r = (const float*)d_in[6];
    const float* w2r = (const float*)d_in[7];
    const float* w3r = (const float*)d_in[8];
    float* out = (float*)d_out;

    float* scores;
    if (out_size >= NTOK*D_DIM + NTOK*E_NUM) {
        scores = out + (size_t)NTOK * D_DIM;
    } else {
        cudaGetSymbolAddress((void**)&scores, g_scores_scratch);
    }

    static int attr_done = 0;
    if (!attr_done) {
        cudaFuncSetAttribute(up_fused,   cudaFuncAttributeMaxDynamicSharedMemorySize, SMEM2_BYTES);
        cudaFuncSetAttribute(down_fused, cudaFuncAttributeMaxDynamicSharedMemorySize, SMEM1_BYTES);
        attr_done = 1;
    }

    init_kernel<<<1, 64>>>();
    gate_kernel<<<NTOK, 128>>>(x, wg, gb, scores);
    scan_kernel<<<1, 32>>>();
    assign_kernel<<<4, 256>>>();

    up_fused<<<dim3(FS_DIM/64, E_NUM + 1, 8), 256, SMEM2_BYTES>>>(x, w1r, w3r, w1s, w3s);
    down_fused<<<dim3(D_DIM/64, E_NUM + 1, 8), 256, SMEM1_BYTES>>>(w2r, w2s, out);

    combine_kernel<<<NTOK, 256>>>(out);
}